// round 2
// baseline (speedup 1.0000x reference)
#include <cuda_runtime.h>
#include <math.h>

// ---------------------------------------------------------------------------
// SlotAttentionMulti — factored formulation.
//   xn = LN(x)                                        (stored once, 268 MB)
//   M_comb = coef * W_qry @ W_k^T                     (256x256, precomputed)
//   per step:
//     q_ln = LN(slot_full); q_proj = q_ln @ M_comb
//     logits[b,s,n] = q_proj[b,s,:] . xn[b,n,:];  e = exp(l - lse_over_slots)
//     rowsum[b,s] = sum_n e       (partials fused into upart)
//     u[b,s,f] = sum_n e * xn[b,n,f];  x_upd = (u/rowsum) @ W_v
//     GRU(x_upd, h) -> x_main; res MLP; means -> slot_view / slot_attr
// ---------------------------------------------------------------------------

#define BVDIM 64        // B*V
#define NTOK  4096
#define FIN   256
#define NS    8
#define SFD   256
#define SVD   64
#define SAD   192
#define FRD   512
#define ROWS  512       // BVDIM*NS
#define COEF  0.08838834764831843f   // 1/sqrt(128)

// ------------------------------ device scratch -----------------------------
__device__ float g_xn[(size_t)BVDIM * NTOK * FIN];       // 268 MB
__device__ float g_e[(size_t)BVDIM * NS * NTOK];         // exp(l - lse_s)
__device__ float g_upart[16 * ROWS * SFD];
__device__ float g_rspart[16 * ROWS];
__device__ float g_upre[ROWS * SFD];
__device__ float g_qln[ROWS * SFD];
__device__ float g_qproj[ROWS * SFD];
__device__ float g_h[ROWS * SFD];
__device__ float g_gi[ROWS * 3 * SFD];
__device__ float g_gh[ROWS * 3 * SFD];
__device__ float g_xmain[ROWS * SFD];
__device__ float g_rln[ROWS * SFD];
__device__ float g_t1[ROWS * FRD];
__device__ float g_xupd[ROWS * SFD];
__device__ float g_snew[ROWS * SFD];
__device__ float g_sview[BVDIM * SVD];
__device__ float g_sattr[16 * NS * SAD];
__device__ float g_Mcomb[SFD * SFD];

// ------------------------------ helpers ------------------------------------
__device__ __forceinline__ void block_sum2(float& s1, float& s2, float* sm16) {
    #pragma unroll
    for (int o = 16; o; o >>= 1) {
        s1 += __shfl_xor_sync(0xffffffffu, s1, o);
        s2 += __shfl_xor_sync(0xffffffffu, s2, o);
    }
    int w = threadIdx.x >> 5, lane = threadIdx.x & 31;
    if (lane == 0) { sm16[w] = s1; sm16[8 + w] = s2; }
    __syncthreads();
    s1 = 0.f; s2 = 0.f;
    #pragma unroll
    for (int i = 0; i < 8; i++) { s1 += sm16[i]; s2 += sm16[8 + i]; }
}

__device__ __forceinline__ float sigmoidf(float x) { return 1.f / (1.f + expf(-x)); }

// ------------------------------ LN over x ----------------------------------
__global__ void __launch_bounds__(256) ln_x_kernel(
    const float* __restrict__ x, const float* __restrict__ g, const float* __restrict__ b)
{
    int w = threadIdx.x >> 5, lane = threadIdx.x & 31;
    size_t row = (size_t)blockIdx.x * 8 + w;
    const float4* xr = (const float4*)(x + row * 256);
    float4 v0 = xr[lane], v1 = xr[lane + 32];
    float s = v0.x + v0.y + v0.z + v0.w + v1.x + v1.y + v1.z + v1.w;
    float ss = v0.x*v0.x + v0.y*v0.y + v0.z*v0.z + v0.w*v0.w
             + v1.x*v1.x + v1.y*v1.y + v1.z*v1.z + v1.w*v1.w;
    #pragma unroll
    for (int o = 16; o; o >>= 1) {
        s  += __shfl_xor_sync(0xffffffffu, s, o);
        ss += __shfl_xor_sync(0xffffffffu, ss, o);
    }
    float mu = s * (1.f / 256.f);
    float var = ss * (1.f / 256.f) - mu * mu;
    float rs = rsqrtf(var + 1e-5f);
    const float4* g4 = (const float4*)g;
    const float4* b4 = (const float4*)b;
    float4 G0 = g4[lane], G1 = g4[lane + 32], B0 = b4[lane], B1 = b4[lane + 32];
    float4 o0, o1;
    o0.x = (v0.x - mu) * rs * G0.x + B0.x;  o0.y = (v0.y - mu) * rs * G0.y + B0.y;
    o0.z = (v0.z - mu) * rs * G0.z + B0.z;  o0.w = (v0.w - mu) * rs * G0.w + B0.w;
    o1.x = (v1.x - mu) * rs * G1.x + B1.x;  o1.y = (v1.y - mu) * rs * G1.y + B1.y;
    o1.z = (v1.z - mu) * rs * G1.z + B1.z;  o1.w = (v1.w - mu) * rs * G1.w + B1.w;
    float4* xo = (float4*)(g_xn + row * 256);
    xo[lane] = o0; xo[lane + 32] = o1;
}

// ------------------------------ slot init ----------------------------------
__global__ void __launch_bounds__(256) slots_init_kernel(
    const float* __restrict__ noise_view, const float* __restrict__ noise_attr,
    const float* __restrict__ view_loc, const float* __restrict__ view_log_scl,
    const float* __restrict__ attr_loc, const float* __restrict__ attr_log_scl)
{
    int i = blockIdx.x * 256 + threadIdx.x;
    if (i < BVDIM * SVD) {
        int c = i & 63;
        g_sview[i] = view_loc[c] + expf(view_log_scl[c]) * noise_view[i];
    } else if (i < BVDIM * SVD + 16 * NS * SAD) {
        int j = i - BVDIM * SVD;
        int c = j % SAD;
        g_sattr[j] = attr_loc[c] + expf(attr_log_scl[c]) * noise_attr[j];
    }
}

// ------------------------------ generic fp32 GEMM --------------------------
// C[M,N] = alpha * A @ op(B) (+ bias) (+ D) (relu).  M,N mult of 64, K mult of 16.
template<bool TRANSB, bool RELU, bool HASBIAS, bool HASD>
__global__ void __launch_bounds__(256) gemm_k(
    int M, int N, int K,
    const float* __restrict__ A, int lda,
    const float* __restrict__ B, int ldb,
    float* __restrict__ C, int ldc,
    const float* __restrict__ bias,
    const float* __restrict__ D,
    float alpha)
{
    __shared__ float As[16][64];
    __shared__ float Bs[16][64];
    int tid = threadIdx.x;
    int tx = tid & 15, ty = tid >> 4;
    int m0 = blockIdx.y * 64, n0 = blockIdx.x * 64;
    float acc[4][4] = {};
    int ra = tid >> 2, ka = (tid & 3) * 4;
    int kb = tid >> 4, nb = (tid & 15) * 4;
    for (int k0 = 0; k0 < K; k0 += 16) {
        float4 av = *(const float4*)(A + (size_t)(m0 + ra) * lda + k0 + ka);
        As[ka + 0][ra] = av.x; As[ka + 1][ra] = av.y;
        As[ka + 2][ra] = av.z; As[ka + 3][ra] = av.w;
        if (TRANSB) {
            float4 bv = *(const float4*)(B + (size_t)(n0 + ra) * ldb + k0 + ka);
            Bs[ka + 0][ra] = bv.x; Bs[ka + 1][ra] = bv.y;
            Bs[ka + 2][ra] = bv.z; Bs[ka + 3][ra] = bv.w;
        } else {
            float4 bv = *(const float4*)(B + (size_t)(k0 + kb) * ldb + n0 + nb);
            *(float4*)&Bs[kb][nb] = bv;
        }
        __syncthreads();
        #pragma unroll
        for (int kk = 0; kk < 16; kk++) {
            float4 a4 = *(const float4*)&As[kk][ty * 4];
            float4 b4 = *(const float4*)&Bs[kk][tx * 4];
            float ar[4] = {a4.x, a4.y, a4.z, a4.w};
            float br[4] = {b4.x, b4.y, b4.z, b4.w};
            #pragma unroll
            for (int i = 0; i < 4; i++)
                #pragma unroll
                for (int j = 0; j < 4; j++)
                    acc[i][j] += ar[i] * br[j];
        }
        __syncthreads();
    }
    float4 bv4 = make_float4(0.f, 0.f, 0.f, 0.f);
    if (HASBIAS) bv4 = *(const float4*)(bias + n0 + tx * 4);
    #pragma unroll
    for (int i = 0; i < 4; i++) {
        int row = m0 + ty * 4 + i;
        float4 out;
        out.x = acc[i][0] * alpha; out.y = acc[i][1] * alpha;
        out.z = acc[i][2] * alpha; out.w = acc[i][3] * alpha;
        if (HASBIAS) { out.x += bv4.x; out.y += bv4.y; out.z += bv4.z; out.w += bv4.w; }
        if (HASD) {
            float4 dv = *(const float4*)(D + (size_t)row * ldc + n0 + tx * 4);
            out.x += dv.x; out.y += dv.y; out.z += dv.z; out.w += dv.w;
        }
        if (RELU) {
            out.x = fmaxf(out.x, 0.f); out.y = fmaxf(out.y, 0.f);
            out.z = fmaxf(out.z, 0.f); out.w = fmaxf(out.w, 0.f);
        }
        *(float4*)(C + (size_t)row * ldc + n0 + tx * 4) = out;
    }
}

// ------------------------------ slot build + LN(q) -------------------------
__global__ void __launch_bounds__(256) build_slots_kernel(
    const float* __restrict__ lnqg, const float* __restrict__ lnqb)
{
    __shared__ float sm[16];
    int r = blockIdx.x;
    int bv = r >> 3, s = r & 7;
    int b = bv >> 2;
    int t = threadIdx.x;
    float val = (t < SVD) ? g_sview[bv * SVD + t]
                          : g_sattr[(b * NS + s) * SAD + (t - SVD)];
    float s1 = val, s2 = val * val;
    block_sum2(s1, s2, sm);
    float mu = s1 * (1.f / 256.f);
    float var = s2 * (1.f / 256.f) - mu * mu;
    float rs = rsqrtf(var + 1e-5f);
    g_h[r * 256 + t] = val;
    g_qln[r * 256 + t] = (val - mu) * rs * lnqg[t] + lnqb[t];
}

// ------------------------------ logits + slot-softmax ----------------------
// e[b,s,n] = exp(logits - lse_over_slots).  Warp handles 2 token rows; after
// the xor-reduction every lane holds all 8 slot logits, so the slot softmax
// (log_softmax axis=-2) is computed in-register.
__global__ void __launch_bounds__(256) logits_kernel()
{
    __shared__ float q_sm[8 * 256];
    int bid = blockIdx.x;
    int b = bid >> 8;            // 64 batches
    int chunk = bid & 255;       // 256 chunks * 16 rows
    for (int i = threadIdx.x; i < 2048; i += 256)
        q_sm[i] = g_qproj[b * 2048 + i];
    __syncthreads();
    int w = threadIdx.x >> 5, lane = threadIdx.x & 31;
    int n = chunk * 16 + w * 2;
    const float* xr = g_xn + ((size_t)b * NTOK + n) * 256;
    float a0[8] = {}, a1[8] = {};
    #pragma unroll
    for (int j = 0; j < 8; j++) {
        int f = lane + 32 * j;
        float x0 = xr[f];
        float x1 = xr[256 + f];
        #pragma unroll
        for (int s = 0; s < 8; s++) {
            float q = q_sm[s * 256 + f];
            a0[s] += x0 * q;
            a1[s] += x1 * q;
        }
    }
    #pragma unroll
    for (int o = 16; o; o >>= 1)
        #pragma unroll
        for (int s = 0; s < 8; s++) {
            a0[s] += __shfl_xor_sync(0xffffffffu, a0[s], o);
            a1[s] += __shfl_xor_sync(0xffffffffu, a1[s], o);
        }
    // slot softmax (all lanes redundantly, then lane<8 writes)
    float m0 = a0[0], m1 = a1[0];
    #pragma unroll
    for (int s = 1; s < 8; s++) { m0 = fmaxf(m0, a0[s]); m1 = fmaxf(m1, a1[s]); }
    float s0 = 0.f, s1 = 0.f;
    #pragma unroll
    for (int s = 0; s < 8; s++) { s0 += expf(a0[s] - m0); s1 += expf(a1[s] - m1); }
    float lse0 = m0 + logf(s0), lse1 = m1 + logf(s1);
    if (lane < 8) {
        g_e[((size_t)b * 8 + lane) * NTOK + n]     = expf(a0[lane] - lse0);
        g_e[((size_t)b * 8 + lane) * NTOK + n + 1] = expf(a1[lane] - lse1);
    }
}

// ------------------------------ attn @ xn partials + rowsum partials -------
__global__ void __launch_bounds__(256) upart_kernel()
{
    __shared__ float e_sm[8 * 256];
    int b = blockIdx.x >> 4;
    int c = blockIdx.x & 15;
    int n0 = c * 256;
    for (int i = threadIdx.x; i < 2048; i += 256) {
        int s = i >> 8, nn = i & 255;
        e_sm[i] = g_e[((size_t)b * 8 + s) * NTOK + n0 + nn];
    }
    __syncthreads();
    // rowsum partials: warp w (w<8) reduces slot w over this 256-token chunk
    {
        int w = threadIdx.x >> 5, lane = threadIdx.x & 31;
        if (w < 8) {
            float rs = 0.f;
            #pragma unroll
            for (int j = 0; j < 8; j++) rs += e_sm[w * 256 + lane + 32 * j];
            #pragma unroll
            for (int o = 16; o; o >>= 1) rs += __shfl_xor_sync(0xffffffffu, rs, o);
            if (lane == 0) g_rspart[c * ROWS + b * 8 + w] = rs;
        }
    }
    int f = threadIdx.x;
    float acc[8] = {};
    const float* xb = g_xn + ((size_t)b * NTOK + n0) * 256 + f;
    for (int n = 0; n < 256; n += 4) {
        float x0 = xb[(size_t)(n + 0) * 256];
        float x1 = xb[(size_t)(n + 1) * 256];
        float x2 = xb[(size_t)(n + 2) * 256];
        float x3 = xb[(size_t)(n + 3) * 256];
        #pragma unroll
        for (int s = 0; s < 8; s++) {
            float4 ev = *(const float4*)&e_sm[s * 256 + n];
            acc[s] += ev.x * x0 + ev.y * x1 + ev.z * x2 + ev.w * x3;
        }
    }
    #pragma unroll
    for (int s = 0; s < 8; s++)
        g_upart[((size_t)c * ROWS + b * 8 + s) * 256 + f] = acc[s];
}

// ------------------------------ reduce partials + normalize ----------------
__global__ void __launch_bounds__(256) ureduce_kernel()
{
    int r = blockIdx.x;
    int f = threadIdx.x;
    float s = 0.f;
    #pragma unroll
    for (int c = 0; c < 16; c++)
        s += g_upart[((size_t)c * ROWS + r) * 256 + f];
    float rs = 0.f;
    #pragma unroll
    for (int c = 0; c < 16; c++) rs += g_rspart[c * ROWS + r];
    g_upre[r * 256 + f] = s / rs;
}

// ------------------------------ GRU + LN(x_main) ---------------------------
__global__ void __launch_bounds__(256) gru_kernel(
    const float* __restrict__ lnrg, const float* __restrict__ lnrb)
{
    __shared__ float sm[16];
    int r = blockIdx.x;
    int j = threadIdx.x;
    float ir = g_gi[r * 768 + j],       hr = g_gh[r * 768 + j];
    float iz = g_gi[r * 768 + 256 + j], hz = g_gh[r * 768 + 256 + j];
    float inn = g_gi[r * 768 + 512 + j], hn = g_gh[r * 768 + 512 + j];
    float rg = sigmoidf(ir + hr);
    float z = sigmoidf(iz + hz);
    float nn = tanhf(inn + rg * hn);
    float hv = g_h[r * 256 + j];
    float xm = (1.f - z) * nn + z * hv;
    g_xmain[r * 256 + j] = xm;
    float s1 = xm, s2 = xm * xm;
    block_sum2(s1, s2, sm);
    float mu = s1 * (1.f / 256.f);
    float var = s2 * (1.f / 256.f) - mu * mu;
    float rs = rsqrtf(var + 1e-5f);
    g_rln[r * 256 + j] = (xm - mu) * rs * lnrg[j] + lnrb[j];
}

// ------------------------------ means -> slot_view / slot_attr -------------
__global__ void __launch_bounds__(256) means_kernel()
{
    int i = blockIdx.x * 256 + threadIdx.x;
    if (i < BVDIM * SVD) {
        int bv = i >> 6, c = i & 63;
        float s = 0.f;
        #pragma unroll
        for (int s8 = 0; s8 < 8; s8++) s += g_snew[((bv << 3) + s8) * 256 + c];
        g_sview[i] = s * 0.125f;
    } else if (i < BVDIM * SVD + 16 * NS * SAD) {
        int j = i - BVDIM * SVD;
        int bs = j / SAD, c = j % SAD;
        int b = bs >> 3, s = bs & 7;
        float t = 0.f;
        #pragma unroll
        for (int v = 0; v < 4; v++)
            t += g_snew[((b * 4 + v) * 8 + s) * 256 + SVD + c];
        g_sattr[j] = t * 0.25f;
    }
}

// ------------------------------ output copy --------------------------------
__global__ void __launch_bounds__(256) copy_out_kernel(float* __restrict__ out, int out_size)
{
    int i = blockIdx.x * 256 + threadIdx.x;
    if (i >= out_size) return;
    if (i < BVDIM * SVD) out[i] = g_sview[i];
    else out[i] = g_sattr[i - BVDIM * SVD];
}

// ------------------------------ host side ----------------------------------
template <typename T>
static float* sym_addr(const T& sym) {
    void* p = nullptr;
    cudaGetSymbolAddress(&p, sym);
    return (float*)p;
}

static void gemm(int M, int N, int K,
                 const float* A, int lda, const float* B, int ldb,
                 float* C, int ldc,
                 const float* bias, const float* D, float alpha,
                 bool transb, bool relu)
{
    dim3 grid(N / 64, M / 64);
    if (transb) {
        if (bias) gemm_k<true, false, true, false><<<grid, 256>>>(M, N, K, A, lda, B, ldb, C, ldc, bias, D, alpha);
        else      gemm_k<true, false, false, false><<<grid, 256>>>(M, N, K, A, lda, B, ldb, C, ldc, bias, D, alpha);
    } else {
        if (relu)       gemm_k<false, true, true, false><<<grid, 256>>>(M, N, K, A, lda, B, ldb, C, ldc, bias, D, alpha);
        else if (D)     gemm_k<false, false, true, true><<<grid, 256>>>(M, N, K, A, lda, B, ldb, C, ldc, bias, D, alpha);
        else if (bias)  gemm_k<false, false, true, false><<<grid, 256>>>(M, N, K, A, lda, B, ldb, C, ldc, bias, D, alpha);
        else            gemm_k<false, false, false, false><<<grid, 256>>>(M, N, K, A, lda, B, ldb, C, ldc, bias, D, alpha);
    }
}

extern "C" void kernel_launch(void* const* d_in, const int* in_sizes, int n_in,
                              void* d_out, int out_size)
{
    const float* x             = (const float*)d_in[0];
    const float* noise_view    = (const float*)d_in[1];
    const float* noise_attr    = (const float*)d_in[2];
    const float* view_loc      = (const float*)d_in[3];
    const float* view_log_scl  = (const float*)d_in[4];
    const float* attr_loc      = (const float*)d_in[5];
    const float* attr_log_scl  = (const float*)d_in[6];
    const float* ln_kv_g       = (const float*)d_in[7];
    const float* ln_kv_b       = (const float*)d_in[8];
    const float* W_kv          = (const float*)d_in[9];
    const float* ln_q_g        = (const float*)d_in[10];
    const float* ln_q_b        = (const float*)d_in[11];
    const float* W_qry         = (const float*)d_in[12];
    const float* w_ih          = (const float*)d_in[13];
    const float* w_hh          = (const float*)d_in[14];
    const float* b_ih          = (const float*)d_in[15];
    const float* b_hh          = (const float*)d_in[16];
    const float* ln_r_g        = (const float*)d_in[17];
    const float* ln_r_b        = (const float*)d_in[18];
    const float* W_r1          = (const float*)d_in[19];
    const float* b_r1          = (const float*)d_in[20];
    const float* W_r2          = (const float*)d_in[21];
    const float* b_r2          = (const float*)d_in[22];

    float* pMcomb = sym_addr(g_Mcomb);
    float* pqln   = sym_addr(g_qln);
    float* pqproj = sym_addr(g_qproj);
    float* pupre  = sym_addr(g_upre);
    float* pxupd  = sym_addr(g_xupd);
    float* ph     = sym_addr(g_h);
    float* pgi    = sym_addr(g_gi);
    float* pgh    = sym_addr(g_gh);
    float* prln   = sym_addr(g_rln);
    float* pt1    = sym_addr(g_t1);
    float* pxmain = sym_addr(g_xmain);
    float* psnew  = sym_addr(g_snew);

    // xn = LN(x)
    ln_x_kernel<<<32768, 256>>>(x, ln_kv_g, ln_kv_b);
    // slot init
    slots_init_kernel<<<112, 256>>>(noise_view, noise_attr, view_loc, view_log_scl,
                                    attr_loc, attr_log_scl);
    // M_comb = coef * W_qry @ W_k^T      (W_k = W_kv[:, :128], TRANSB on W_kv)
    gemm(256, 256, 128, W_qry, 128, W_kv, 384, pMcomb, 256, nullptr, nullptr, COEF, true, false);

    for (int step = 0; step < 3; step++) {
        build_slots_kernel<<<ROWS, 256>>>(ln_q_g, ln_q_b);
        // q_proj = q_ln @ M_comb
        gemm(ROWS, 256, 256, pqln, 256, pMcomb, 256, pqproj, 256, nullptr, nullptr, 1.f, false, false);
        logits_kernel<<<64 * 256, 256>>>();
        upart_kernel<<<1024, 256>>>();
        ureduce_kernel<<<ROWS, 256>>>();
        // x_upd = upre @ W_v   (W_v = W_kv[:, 128:], normal layout, ldb=384)
        gemm(ROWS, 256, 256, pupre, 256, W_kv + 128, 384, pxupd, 256, nullptr, nullptr, 1.f, false, false);
        // gi = x_upd @ w_ih^T + b_ih ; gh = h @ w_hh^T + b_hh
        gemm(ROWS, 768, 256, pxupd, 256, w_ih, 256, pgi, 768, b_ih, nullptr, 1.f, true, false);
        gemm(ROWS, 768, 256, ph,    256, w_hh, 256, pgh, 768, b_hh, nullptr, 1.f, true, false);
        gru_kernel<<<ROWS, 256>>>(ln_r_g, ln_r_b);
        // t1 = relu(r_ln @ W_r1 + b_r1)
        gemm(ROWS, 512, 256, prln, 256, W_r1, 512, pt1, 512, b_r1, nullptr, 1.f, false, true);
        // slot_new = x_main + t1 @ W_r2 + b_r2
        gemm(ROWS, 256, 512, pt1, 512, W_r2, 256, psnew, 256, b_r2, pxmain, 1.f, false, false);
        means_kernel<<<112, 256>>>();
    }

    copy_out_kernel<<<(out_size + 255) / 256, 256>>>((float*)d_out, out_size);
}

// round 3
// speedup vs baseline: 1.2048x; 1.2048x over previous
#include <cuda_runtime.h>
#include <cuda_bf16.h>
#include <math.h>

// ---------------------------------------------------------------------------
// SlotAttentionMulti — factored formulation, bf16 xn, fused attention.
//   xnb = bf16(LN(x))                                 (stored once, 134 MB)
//   M_comb = coef * W_qry @ W_k^T                     (256x256, precomputed)
//   per step:
//     q_ln = LN(slot_full); q_proj = q_ln @ M_comb
//     fused kernel per (b, 128-token chunk):
//       logits[s,t] = q_proj . xnb ; e = exp(l - lse_over_slots)
//       rowsum partials ; upart[s,f] = sum_t e * xnb
//     ureduce: x_pre = (sum_c upart) / (sum_c rowsum)
//     x_upd = x_pre @ W_v ; GRU ; res MLP ; means
// ---------------------------------------------------------------------------

#define BVDIM 64        // B*V
#define NTOK  4096
#define FIN   256
#define NS    8
#define SFD   256
#define SVD   64
#define SAD   192
#define FRD   512
#define ROWS  512       // BVDIM*NS
#define NCHUNK 32       // 4096/128 token chunks
#define CHUNK 128
#define COEF  0.08838834764831843f   // 1/sqrt(128)

// ------------------------------ device scratch -----------------------------
__device__ __nv_bfloat16 g_xnb[(size_t)BVDIM * NTOK * FIN];   // 134 MB
__device__ float g_upart[(size_t)NCHUNK * ROWS * SFD];        // 16 MB
__device__ float g_rspart[NCHUNK * ROWS];
__device__ float g_upre[ROWS * SFD];
__device__ float g_qln[ROWS * SFD];
__device__ float g_qproj[ROWS * SFD];
__device__ float g_h[ROWS * SFD];
__device__ float g_gi[ROWS * 3 * SFD];
__device__ float g_gh[ROWS * 3 * SFD];
__device__ float g_xmain[ROWS * SFD];
__device__ float g_rln[ROWS * SFD];
__device__ float g_t1[ROWS * FRD];
__device__ float g_xupd[ROWS * SFD];
__device__ float g_snew[ROWS * SFD];
__device__ float g_sview[BVDIM * SVD];
__device__ float g_sattr[16 * NS * SAD];
__device__ float g_Mcomb[SFD * SFD];

// ------------------------------ helpers ------------------------------------
__device__ __forceinline__ void block_sum2(float& s1, float& s2, float* sm16) {
    #pragma unroll
    for (int o = 16; o; o >>= 1) {
        s1 += __shfl_xor_sync(0xffffffffu, s1, o);
        s2 += __shfl_xor_sync(0xffffffffu, s2, o);
    }
    int w = threadIdx.x >> 5, lane = threadIdx.x & 31;
    if (lane == 0) { sm16[w] = s1; sm16[8 + w] = s2; }
    __syncthreads();
    s1 = 0.f; s2 = 0.f;
    #pragma unroll
    for (int i = 0; i < 8; i++) { s1 += sm16[i]; s2 += sm16[8 + i]; }
}

__device__ __forceinline__ float sigmoidf(float x) { return 1.f / (1.f + expf(-x)); }

// ------------------------------ LN over x -> bf16 --------------------------
__global__ void __launch_bounds__(256) ln_x_kernel(
    const float* __restrict__ x, const float* __restrict__ g, const float* __restrict__ b)
{
    int w = threadIdx.x >> 5, lane = threadIdx.x & 31;
    size_t row = (size_t)blockIdx.x * 8 + w;
    const float4* xr = (const float4*)(x + row * 256);
    float4 v0 = xr[lane], v1 = xr[lane + 32];
    float s = v0.x + v0.y + v0.z + v0.w + v1.x + v1.y + v1.z + v1.w;
    float ss = v0.x*v0.x + v0.y*v0.y + v0.z*v0.z + v0.w*v0.w
             + v1.x*v1.x + v1.y*v1.y + v1.z*v1.z + v1.w*v1.w;
    #pragma unroll
    for (int o = 16; o; o >>= 1) {
        s  += __shfl_xor_sync(0xffffffffu, s, o);
        ss += __shfl_xor_sync(0xffffffffu, ss, o);
    }
    float mu = s * (1.f / 256.f);
    float var = ss * (1.f / 256.f) - mu * mu;
    float rs = rsqrtf(var + 1e-5f);
    const float4* g4 = (const float4*)g;
    const float4* b4 = (const float4*)b;
    float4 G0 = g4[lane], G1 = g4[lane + 32], B0 = b4[lane], B1 = b4[lane + 32];
    __nv_bfloat162 p0 = __floats2bfloat162_rn((v0.x - mu) * rs * G0.x + B0.x,
                                              (v0.y - mu) * rs * G0.y + B0.y);
    __nv_bfloat162 p1 = __floats2bfloat162_rn((v0.z - mu) * rs * G0.z + B0.z,
                                              (v0.w - mu) * rs * G0.w + B0.w);
    __nv_bfloat162 p2 = __floats2bfloat162_rn((v1.x - mu) * rs * G1.x + B1.x,
                                              (v1.y - mu) * rs * G1.y + B1.y);
    __nv_bfloat162 p3 = __floats2bfloat162_rn((v1.z - mu) * rs * G1.z + B1.z,
                                              (v1.w - mu) * rs * G1.w + B1.w);
    uint2* xo = (uint2*)(g_xnb + row * 256);
    uint2 u0, u1;
    u0.x = *(unsigned*)&p0; u0.y = *(unsigned*)&p1;
    u1.x = *(unsigned*)&p2; u1.y = *(unsigned*)&p3;
    xo[lane] = u0; xo[lane + 32] = u1;
}

// ------------------------------ slot init ----------------------------------
__global__ void __launch_bounds__(256) slots_init_kernel(
    const float* __restrict__ noise_view, const float* __restrict__ noise_attr,
    const float* __restrict__ view_loc, const float* __restrict__ view_log_scl,
    const float* __restrict__ attr_loc, const float* __restrict__ attr_log_scl)
{
    int i = blockIdx.x * 256 + threadIdx.x;
    if (i < BVDIM * SVD) {
        int c = i & 63;
        g_sview[i] = view_loc[c] + expf(view_log_scl[c]) * noise_view[i];
    } else if (i < BVDIM * SVD + 16 * NS * SAD) {
        int j = i - BVDIM * SVD;
        int c = j % SAD;
        g_sattr[j] = attr_loc[c] + expf(attr_log_scl[c]) * noise_attr[j];
    }
}

// ------------------------------ generic fp32 GEMM --------------------------
template<bool TRANSB, bool RELU, bool HASBIAS, bool HASD>
__global__ void __launch_bounds__(256) gemm_k(
    int M, int N, int K,
    const float* __restrict__ A, int lda,
    const float* __restrict__ B, int ldb,
    float* __restrict__ C, int ldc,
    const float* __restrict__ bias,
    const float* __restrict__ D,
    float alpha)
{
    __shared__ float As[16][64];
    __shared__ float Bs[16][64];
    int tid = threadIdx.x;
    int tx = tid & 15, ty = tid >> 4;
    int m0 = blockIdx.y * 64, n0 = blockIdx.x * 64;
    float acc[4][4] = {};
    int ra = tid >> 2, ka = (tid & 3) * 4;
    int kb = tid >> 4, nb = (tid & 15) * 4;
    for (int k0 = 0; k0 < K; k0 += 16) {
        float4 av = *(const float4*)(A + (size_t)(m0 + ra) * lda + k0 + ka);
        As[ka + 0][ra] = av.x; As[ka + 1][ra] = av.y;
        As[ka + 2][ra] = av.z; As[ka + 3][ra] = av.w;
        if (TRANSB) {
            float4 bv = *(const float4*)(B + (size_t)(n0 + ra) * ldb + k0 + ka);
            Bs[ka + 0][ra] = bv.x; Bs[ka + 1][ra] = bv.y;
            Bs[ka + 2][ra] = bv.z; Bs[ka + 3][ra] = bv.w;
        } else {
            float4 bv = *(const float4*)(B + (size_t)(k0 + kb) * ldb + n0 + nb);
            *(float4*)&Bs[kb][nb] = bv;
        }
        __syncthreads();
        #pragma unroll
        for (int kk = 0; kk < 16; kk++) {
            float4 a4 = *(const float4*)&As[kk][ty * 4];
            float4 b4 = *(const float4*)&Bs[kk][tx * 4];
            float ar[4] = {a4.x, a4.y, a4.z, a4.w};
            float br[4] = {b4.x, b4.y, b4.z, b4.w};
            #pragma unroll
            for (int i = 0; i < 4; i++)
                #pragma unroll
                for (int j = 0; j < 4; j++)
                    acc[i][j] += ar[i] * br[j];
        }
        __syncthreads();
    }
    float4 bv4 = make_float4(0.f, 0.f, 0.f, 0.f);
    if (HASBIAS) bv4 = *(const float4*)(bias + n0 + tx * 4);
    #pragma unroll
    for (int i = 0; i < 4; i++) {
        int row = m0 + ty * 4 + i;
        float4 out;
        out.x = acc[i][0] * alpha; out.y = acc[i][1] * alpha;
        out.z = acc[i][2] * alpha; out.w = acc[i][3] * alpha;
        if (HASBIAS) { out.x += bv4.x; out.y += bv4.y; out.z += bv4.z; out.w += bv4.w; }
        if (HASD) {
            float4 dv = *(const float4*)(D + (size_t)row * ldc + n0 + tx * 4);
            out.x += dv.x; out.y += dv.y; out.z += dv.z; out.w += dv.w;
        }
        if (RELU) {
            out.x = fmaxf(out.x, 0.f); out.y = fmaxf(out.y, 0.f);
            out.z = fmaxf(out.z, 0.f); out.w = fmaxf(out.w, 0.f);
        }
        *(float4*)(C + (size_t)row * ldc + n0 + tx * 4) = out;
    }
}

// ------------------------------ slot build + LN(q) -------------------------
__global__ void __launch_bounds__(256) build_slots_kernel(
    const float* __restrict__ lnqg, const float* __restrict__ lnqb)
{
    __shared__ float sm[16];
    int r = blockIdx.x;
    int bv = r >> 3, s = r & 7;
    int b = bv >> 2;
    int t = threadIdx.x;
    float val = (t < SVD) ? g_sview[bv * SVD + t]
                          : g_sattr[(b * NS + s) * SAD + (t - SVD)];
    float s1 = val, s2 = val * val;
    block_sum2(s1, s2, sm);
    float mu = s1 * (1.f / 256.f);
    float var = s2 * (1.f / 256.f) - mu * mu;
    float rs = rsqrtf(var + 1e-5f);
    g_h[r * 256 + t] = val;
    g_qln[r * 256 + t] = (val - mu) * rs * lnqg[t] + lnqb[t];
}

// ------------------------------ fused attention ----------------------------
// Block = (batch b, 128-token chunk c). Stages the bf16 xn tile in smem once.
// Phase 1: warp computes logits for 2 tokens at a time (q in registers),
//          slot log-softmax in-register, e -> smem.
// Phase 2: rowsum partials (8 warps) + per-f accumulation of e*xn -> upart.
__global__ void __launch_bounds__(256) attn_fused_kernel()
{
    extern __shared__ char smraw[];
    __nv_bfloat16* xs = (__nv_bfloat16*)smraw;         // 128*256 bf16 = 64 KB
    float* es = (float*)(smraw + CHUNK * 256 * 2);     // 8*128 f32 = 4 KB

    int b = blockIdx.x >> 5;
    int c = blockIdx.x & 31;
    int n0 = c * CHUNK;

    // stage xn tile
    {
        const uint4* src = (const uint4*)(g_xnb + ((size_t)b * NTOK + n0) * 256);
        uint4* dst = (uint4*)xs;
        #pragma unroll
        for (int i = 0; i < 16; i++)
            dst[threadIdx.x + 256 * i] = src[threadIdx.x + 256 * i];
    }

    int w = threadIdx.x >> 5, lane = threadIdx.x & 31;
    // q in registers: q[s][j] for f = lane + 32j  (coalesced loads)
    float q[8][8];
    {
        const float* qb = g_qproj + b * 2048;
        #pragma unroll
        for (int s = 0; s < 8; s++)
            #pragma unroll
            for (int j = 0; j < 8; j++)
                q[s][j] = qb[s * 256 + lane + 32 * j];
    }
    __syncthreads();

    // phase 1: logits + slot softmax
    #pragma unroll 1
    for (int p = 0; p < 8; p++) {
        int t0 = w * 16 + p * 2;
        const __nv_bfloat16* xp = xs + t0 * 256;
        float a0[8] = {}, a1[8] = {};
        #pragma unroll
        for (int j = 0; j < 8; j++) {
            float x0 = __bfloat162float(xp[lane + 32 * j]);
            float x1 = __bfloat162float(xp[256 + lane + 32 * j]);
            #pragma unroll
            for (int s = 0; s < 8; s++) {
                a0[s] += x0 * q[s][j];
                a1[s] += x1 * q[s][j];
            }
        }
        #pragma unroll
        for (int o = 16; o; o >>= 1)
            #pragma unroll
            for (int s = 0; s < 8; s++) {
                a0[s] += __shfl_xor_sync(0xffffffffu, a0[s], o);
                a1[s] += __shfl_xor_sync(0xffffffffu, a1[s], o);
            }
        float m0 = a0[0], m1 = a1[0];
        #pragma unroll
        for (int s = 1; s < 8; s++) { m0 = fmaxf(m0, a0[s]); m1 = fmaxf(m1, a1[s]); }
        float s0 = 0.f, s1 = 0.f;
        #pragma unroll
        for (int s = 0; s < 8; s++) { s0 += __expf(a0[s] - m0); s1 += __expf(a1[s] - m1); }
        float lse0 = m0 + __logf(s0), lse1 = m1 + __logf(s1);
        if (lane < 8) {
            es[lane * 128 + t0]     = __expf(a0[lane] - lse0);
            es[lane * 128 + t0 + 1] = __expf(a1[lane] - lse1);
        }
    }
    __syncthreads();

    // rowsum partials: warp w (<8) reduces slot w over the 128-token chunk
    if (w < 8) {
        float r = 0.f;
        #pragma unroll
        for (int j = 0; j < 4; j++) r += es[w * 128 + lane + 32 * j];
        #pragma unroll
        for (int o = 16; o; o >>= 1) r += __shfl_xor_sync(0xffffffffu, r, o);
        if (lane == 0) g_rspart[c * ROWS + b * 8 + w] = r;
    }

    // phase 2: upart[s][f] = sum_t e[s][t] * x[t][f]
    int f = threadIdx.x;
    float acc[8] = {};
    #pragma unroll 4
    for (int t = 0; t < 128; t += 4) {
        float x0 = __bfloat162float(xs[(t + 0) * 256 + f]);
        float x1 = __bfloat162float(xs[(t + 1) * 256 + f]);
        float x2 = __bfloat162float(xs[(t + 2) * 256 + f]);
        float x3 = __bfloat162float(xs[(t + 3) * 256 + f]);
        #pragma unroll
        for (int s = 0; s < 8; s++) {
            float4 ev = *(const float4*)&es[s * 128 + t];
            acc[s] += ev.x * x0 + ev.y * x1 + ev.z * x2 + ev.w * x3;
        }
    }
    #pragma unroll
    for (int s = 0; s < 8; s++)
        g_upart[((size_t)c * ROWS + b * 8 + s) * 256 + f] = acc[s];
}

// ------------------------------ reduce partials + normalize ----------------
__global__ void __launch_bounds__(256) ureduce_kernel()
{
    int r = blockIdx.x;
    int f = threadIdx.x;
    float s = 0.f;
    #pragma unroll
    for (int c = 0; c < NCHUNK; c++)
        s += g_upart[((size_t)c * ROWS + r) * 256 + f];
    float rs = 0.f;
    #pragma unroll
    for (int c = 0; c < NCHUNK; c++) rs += g_rspart[c * ROWS + r];
    g_upre[r * 256 + f] = s / rs;
}

// ------------------------------ GRU + LN(x_main) ---------------------------
__global__ void __launch_bounds__(256) gru_kernel(
    const float* __restrict__ lnrg, const float* __restrict__ lnrb)
{
    __shared__ float sm[16];
    int r = blockIdx.x;
    int j = threadIdx.x;
    float ir = g_gi[r * 768 + j],       hr = g_gh[r * 768 + j];
    float iz = g_gi[r * 768 + 256 + j], hz = g_gh[r * 768 + 256 + j];
    float inn = g_gi[r * 768 + 512 + j], hn = g_gh[r * 768 + 512 + j];
    float rg = sigmoidf(ir + hr);
    float z = sigmoidf(iz + hz);
    float nn = tanhf(inn + rg * hn);
    float hv = g_h[r * 256 + j];
    float xm = (1.f - z) * nn + z * hv;
    g_xmain[r * 256 + j] = xm;
    float s1 = xm, s2 = xm * xm;
    block_sum2(s1, s2, sm);
    float mu = s1 * (1.f / 256.f);
    float var = s2 * (1.f / 256.f) - mu * mu;
    float rs = rsqrtf(var + 1e-5f);
    g_rln[r * 256 + j] = (xm - mu) * rs * lnrg[j] + lnrb[j];
}

// ------------------------------ means -> slot_view / slot_attr -------------
__global__ void __launch_bounds__(256) means_kernel()
{
    int i = blockIdx.x * 256 + threadIdx.x;
    if (i < BVDIM * SVD) {
        int bv = i >> 6, c = i & 63;
        float s = 0.f;
        #pragma unroll
        for (int s8 = 0; s8 < 8; s8++) s += g_snew[((bv << 3) + s8) * 256 + c];
        g_sview[i] = s * 0.125f;
    } else if (i < BVDIM * SVD + 16 * NS * SAD) {
        int j = i - BVDIM * SVD;
        int bs = j / SAD, c = j % SAD;
        int b = bs >> 3, s = bs & 7;
        float t = 0.f;
        #pragma unroll
        for (int v = 0; v < 4; v++)
            t += g_snew[((b * 4 + v) * 8 + s) * 256 + SVD + c];
        g_sattr[j] = t * 0.25f;
    }
}

// ------------------------------ output copy --------------------------------
__global__ void __launch_bounds__(256) copy_out_kernel(float* __restrict__ out, int out_size)
{
    int i = blockIdx.x * 256 + threadIdx.x;
    if (i >= out_size) return;
    if (i < BVDIM * SVD) out[i] = g_sview[i];
    else out[i] = g_sattr[i - BVDIM * SVD];
}

// ------------------------------ host side ----------------------------------
template <typename T>
static float* sym_addr(const T& sym) {
    void* p = nullptr;
    cudaGetSymbolAddress(&p, sym);
    return (float*)p;
}

static void gemm(int M, int N, int K,
                 const float* A, int lda, const float* B, int ldb,
                 float* C, int ldc,
                 const float* bias, const float* D, float alpha,
                 bool transb, bool relu)
{
    dim3 grid(N / 64, M / 64);
    if (transb) {
        if (bias) gemm_k<true, false, true, false><<<grid, 256>>>(M, N, K, A, lda, B, ldb, C, ldc, bias, D, alpha);
        else      gemm_k<true, false, false, false><<<grid, 256>>>(M, N, K, A, lda, B, ldb, C, ldc, bias, D, alpha);
    } else {
        if (relu)       gemm_k<false, true, true, false><<<grid, 256>>>(M, N, K, A, lda, B, ldb, C, ldc, bias, D, alpha);
        else if (D)     gemm_k<false, false, true, true><<<grid, 256>>>(M, N, K, A, lda, B, ldb, C, ldc, bias, D, alpha);
        else if (bias)  gemm_k<false, false, true, false><<<grid, 256>>>(M, N, K, A, lda, B, ldb, C, ldc, bias, D, alpha);
        else            gemm_k<false, false, false, false><<<grid, 256>>>(M, N, K, A, lda, B, ldb, C, ldc, bias, D, alpha);
    }
}

extern "C" void kernel_launch(void* const* d_in, const int* in_sizes, int n_in,
                              void* d_out, int out_size)
{
    const float* x             = (const float*)d_in[0];
    const float* noise_view    = (const float*)d_in[1];
    const float* noise_attr    = (const float*)d_in[2];
    const float* view_loc      = (const float*)d_in[3];
    const float* view_log_scl  = (const float*)d_in[4];
    const float* attr_loc      = (const float*)d_in[5];
    const float* attr_log_scl  = (const float*)d_in[6];
    const float* ln_kv_g       = (const float*)d_in[7];
    const float* ln_kv_b       = (const float*)d_in[8];
    const float* W_kv          = (const float*)d_in[9];
    const float* ln_q_g        = (const float*)d_in[10];
    const float* ln_q_b        = (const float*)d_in[11];
    const float* W_qry         = (const float*)d_in[12];
    const float* w_ih          = (const float*)d_in[13];
    const float* w_hh          = (const float*)d_in[14];
    const float* b_ih          = (const float*)d_in[15];
    const float* b_hh          = (const float*)d_in[16];
    const float* ln_r_g        = (const float*)d_in[17];
    const float* ln_r_b        = (const float*)d_in[18];
    const float* W_r1          = (const float*)d_in[19];
    const float* b_r1          = (const float*)d_in[20];
    const float* W_r2          = (const float*)d_in[21];
    const float* b_r2          = (const float*)d_in[22];

    float* pMcomb = sym_addr(g_Mcomb);
    float* pqln   = sym_addr(g_qln);
    float* pqproj = sym_addr(g_qproj);
    float* pupre  = sym_addr(g_upre);
    float* pxupd  = sym_addr(g_xupd);
    float* ph     = sym_addr(g_h);
    float* pgi    = sym_addr(g_gi);
    float* pgh    = sym_addr(g_gh);
    float* prln   = sym_addr(g_rln);
    float* pt1    = sym_addr(g_t1);
    float* pxmain = sym_addr(g_xmain);
    float* psnew  = sym_addr(g_snew);

    const int attn_smem = CHUNK * 256 * 2 + 8 * CHUNK * 4;  // 64KB + 4KB
    static bool attr_set = false;
    if (!attr_set) {
        cudaFuncSetAttribute(attn_fused_kernel,
                             cudaFuncAttributeMaxDynamicSharedMemorySize, attn_smem);
        attr_set = true;
    }

    // xn = bf16(LN(x))
    ln_x_kernel<<<32768, 256>>>(x, ln_kv_g, ln_kv_b);
    // slot init
    slots_init_kernel<<<112, 256>>>(noise_view, noise_attr, view_loc, view_log_scl,
                                    attr_loc, attr_log_scl);
    // M_comb = coef * W_qry @ W_k^T      (W_k = W_kv[:, :128], TRANSB on W_kv)
    gemm(256, 256, 128, W_qry, 128, W_kv, 384, pMcomb, 256, nullptr, nullptr, COEF, true, false);

    for (int step = 0; step < 3; step++) {
        build_slots_kernel<<<ROWS, 256>>>(ln_q_g, ln_q_b);
        // q_proj = q_ln @ M_comb
        gemm(ROWS, 256, 256, pqln, 256, pMcomb, 256, pqproj, 256, nullptr, nullptr, 1.f, false, false);
        attn_fused_kernel<<<BVDIM * NCHUNK, 256, attn_smem>>>();
        ureduce_kernel<<<ROWS, 256>>>();
        // x_upd = upre @ W_v   (W_v = W_kv[:, 128:], normal layout, ldb=384)
        gemm(ROWS, 256, 256, pupre, 256, W_kv + 128, 384, pxupd, 256, nullptr, nullptr, 1.f, false, false);
        // gi = x_upd @ w_ih^T + b_ih ; gh = h @ w_hh^T + b_hh
        gemm(ROWS, 768, 256, pxupd, 256, w_ih, 256, pgi, 768, b_ih, nullptr, 1.f, true, false);
        gemm(ROWS, 768, 256, ph,    256, w_hh, 256, pgh, 768, b_hh, nullptr, 1.f, true, false);
        gru_kernel<<<ROWS, 256>>>(ln_r_g, ln_r_b);
        // t1 = relu(r_ln @ W_r1 + b_r1)
        gemm(ROWS, 512, 256, prln, 256, W_r1, 512, pt1, 512, b_r1, nullptr, 1.f, false, true);
        // slot_new = x_main + t1 @ W_r2 + b_r2
        gemm(ROWS, 256, 512, pt1, 512, W_r2, 256, psnew, 256, b_r2, pxmain, 1.f, false, false);
        means_kernel<<<112, 256>>>();
    }

    copy_out_kernel<<<(out_size + 255) / 256, 256>>>((float*)d_out, out_size);
}

// round 4
// speedup vs baseline: 1.4814x; 1.2296x over previous
#include <cuda_runtime.h>
#include <cuda_bf16.h>
#include <math.h>

// ---------------------------------------------------------------------------
// SlotAttentionMulti — factored formulation, bf16 xn, fused attention v2.
//   xnb = bf16(LN(x))                                 (stored once, 134 MB)
//   M_comb = coef * W_qry @ W_k^T                     (256x256, precomputed)
//   M_vih  = W_v @ w_ih^T                             (256x768, precomputed)
//   per step:
//     q_ln = LN(slot_full); q_proj = q_ln @ M_comb
//     fused attention (b, 128-token chunk):
//       raw logits via split-tree reduce -> smem; per-token slot softmax pass;
//       rowsum partials; upart[s,f] = sum_t e * xnb (f32x2 FFMA)
//     ureduce: upre = (sum_c upart) / (sum_c rowsum)
//     gi = upre @ M_vih + b_ih ; gh = h @ w_hh^T + b_hh ; GRU ; MLP ; means
// ---------------------------------------------------------------------------

#define BVDIM 64
#define NTOK  4096
#define NS    8
#define SVD   64
#define SAD   192
#define ROWS  512
#define NCHUNK 32
#define CHUNK 128
#define COEF  0.08838834764831843f

// ------------------------------ device scratch -----------------------------
__device__ __nv_bfloat16 g_xnb[(size_t)BVDIM * NTOK * 256];
__device__ float g_upart[(size_t)NCHUNK * ROWS * 256];
__device__ float g_rspart[NCHUNK * ROWS];
__device__ float g_upre[ROWS * 256];
__device__ float g_qln[ROWS * 256];
__device__ float g_qproj[ROWS * 256];
__device__ float g_h[ROWS * 256];
__device__ float g_gi[ROWS * 768];
__device__ float g_gh[ROWS * 768];
__device__ float g_xmain[ROWS * 256];
__device__ float g_rln[ROWS * 256];
__device__ float g_t1[ROWS * 512];
__device__ float g_snew[ROWS * 256];
__device__ float g_sview[BVDIM * SVD];
__device__ float g_sattr[16 * NS * SAD];
__device__ float g_Mcomb[256 * 256];
__device__ float g_Mvih[256 * 768];

// ------------------------------ helpers ------------------------------------
__device__ __forceinline__ void block_sum2(float& s1, float& s2, float* sm16) {
    #pragma unroll
    for (int o = 16; o; o >>= 1) {
        s1 += __shfl_xor_sync(0xffffffffu, s1, o);
        s2 += __shfl_xor_sync(0xffffffffu, s2, o);
    }
    int w = threadIdx.x >> 5, lane = threadIdx.x & 31;
    if (lane == 0) { sm16[w] = s1; sm16[8 + w] = s2; }
    __syncthreads();
    s1 = 0.f; s2 = 0.f;
    #pragma unroll
    for (int i = 0; i < 8; i++) { s1 += sm16[i]; s2 += sm16[8 + i]; }
}

__device__ __forceinline__ float sigmoidf(float x) { return 1.f / (1.f + expf(-x)); }

__device__ __forceinline__ unsigned long long pack2(float lo, float hi) {
    unsigned long long r;
    asm("mov.b64 %0, {%1, %2};" : "=l"(r) : "f"(lo), "f"(hi));
    return r;
}
__device__ __forceinline__ void ffma2(unsigned long long& acc,
                                      unsigned long long a, unsigned long long b) {
    asm("fma.rn.f32x2 %0, %1, %2, %0;" : "+l"(acc) : "l"(a), "l"(b));
}
__device__ __forceinline__ float2 unpack2(unsigned long long v) {
    float2 r;
    asm("mov.b64 {%0, %1}, %2;" : "=f"(r.x), "=f"(r.y) : "l"(v));
    return r;
}

// ------------------------------ LN over x -> bf16 --------------------------
__global__ void __launch_bounds__(256) ln_x_kernel(
    const float* __restrict__ x, const float* __restrict__ g, const float* __restrict__ b)
{
    int w = threadIdx.x >> 5, lane = threadIdx.x & 31;
    size_t row = (size_t)blockIdx.x * 8 + w;
    const float4* xr = (const float4*)(x + row * 256);
    float4 v0 = xr[lane], v1 = xr[lane + 32];
    float s = v0.x + v0.y + v0.z + v0.w + v1.x + v1.y + v1.z + v1.w;
    float ss = v0.x*v0.x + v0.y*v0.y + v0.z*v0.z + v0.w*v0.w
             + v1.x*v1.x + v1.y*v1.y + v1.z*v1.z + v1.w*v1.w;
    #pragma unroll
    for (int o = 16; o; o >>= 1) {
        s  += __shfl_xor_sync(0xffffffffu, s, o);
        ss += __shfl_xor_sync(0xffffffffu, ss, o);
    }
    float mu = s * (1.f / 256.f);
    float var = ss * (1.f / 256.f) - mu * mu;
    float rs = rsqrtf(var + 1e-5f);
    const float4* g4 = (const float4*)g;
    const float4* b4 = (const float4*)b;
    float4 G0 = g4[lane], G1 = g4[lane + 32], B0 = b4[lane], B1 = b4[lane + 32];
    __nv_bfloat162 p0 = __floats2bfloat162_rn((v0.x - mu) * rs * G0.x + B0.x,
                                              (v0.y - mu) * rs * G0.y + B0.y);
    __nv_bfloat162 p1 = __floats2bfloat162_rn((v0.z - mu) * rs * G0.z + B0.z,
                                              (v0.w - mu) * rs * G0.w + B0.w);
    __nv_bfloat162 p2 = __floats2bfloat162_rn((v1.x - mu) * rs * G1.x + B1.x,
                                              (v1.y - mu) * rs * G1.y + B1.y);
    __nv_bfloat162 p3 = __floats2bfloat162_rn((v1.z - mu) * rs * G1.z + B1.z,
                                              (v1.w - mu) * rs * G1.w + B1.w);
    uint2* xo = (uint2*)(g_xnb + row * 256);
    uint2 u0, u1;
    u0.x = *(unsigned*)&p0; u0.y = *(unsigned*)&p1;
    u1.x = *(unsigned*)&p2; u1.y = *(unsigned*)&p3;
    xo[lane] = u0; xo[lane + 32] = u1;
}

// ------------------------------ slot init ----------------------------------
__global__ void __launch_bounds__(256) slots_init_kernel(
    const float* __restrict__ noise_view, const float* __restrict__ noise_attr,
    const float* __restrict__ view_loc, const float* __restrict__ view_log_scl,
    const float* __restrict__ attr_loc, const float* __restrict__ attr_log_scl)
{
    int i = blockIdx.x * 256 + threadIdx.x;
    if (i < BVDIM * SVD) {
        int c = i & 63;
        g_sview[i] = view_loc[c] + expf(view_log_scl[c]) * noise_view[i];
    } else if (i < BVDIM * SVD + 16 * NS * SAD) {
        int j = i - BVDIM * SVD;
        int c = j % SAD;
        g_sattr[j] = attr_loc[c] + expf(attr_log_scl[c]) * noise_attr[j];
    }
}

// ------------------------------ generic fp32 GEMM --------------------------
template<bool TRANSB, bool RELU, bool HASBIAS, bool HASD>
__global__ void __launch_bounds__(256) gemm_k(
    int M, int N, int K,
    const float* __restrict__ A, int lda,
    const float* __restrict__ B, int ldb,
    float* __restrict__ C, int ldc,
    const float* __restrict__ bias,
    const float* __restrict__ D,
    float alpha)
{
    __shared__ float As[16][64];
    __shared__ float Bs[16][64];
    int tid = threadIdx.x;
    int tx = tid & 15, ty = tid >> 4;
    int m0 = blockIdx.y * 64, n0 = blockIdx.x * 64;
    float acc[4][4] = {};
    int ra = tid >> 2, ka = (tid & 3) * 4;
    int kb = tid >> 4, nb = (tid & 15) * 4;
    for (int k0 = 0; k0 < K; k0 += 16) {
        float4 av = *(const float4*)(A + (size_t)(m0 + ra) * lda + k0 + ka);
        As[ka + 0][ra] = av.x; As[ka + 1][ra] = av.y;
        As[ka + 2][ra] = av.z; As[ka + 3][ra] = av.w;
        if (TRANSB) {
            float4 bv = *(const float4*)(B + (size_t)(n0 + ra) * ldb + k0 + ka);
            Bs[ka + 0][ra] = bv.x; Bs[ka + 1][ra] = bv.y;
            Bs[ka + 2][ra] = bv.z; Bs[ka + 3][ra] = bv.w;
        } else {
            float4 bv = *(const float4*)(B + (size_t)(k0 + kb) * ldb + n0 + nb);
            *(float4*)&Bs[kb][nb] = bv;
        }
        __syncthreads();
        #pragma unroll
        for (int kk = 0; kk < 16; kk++) {
            float4 a4 = *(const float4*)&As[kk][ty * 4];
            float4 b4 = *(const float4*)&Bs[kk][tx * 4];
            float ar[4] = {a4.x, a4.y, a4.z, a4.w};
            float br[4] = {b4.x, b4.y, b4.z, b4.w};
            #pragma unroll
            for (int i = 0; i < 4; i++)
                #pragma unroll
                for (int j = 0; j < 4; j++)
                    acc[i][j] += ar[i] * br[j];
        }
        __syncthreads();
    }
    float4 bv4 = make_float4(0.f, 0.f, 0.f, 0.f);
    if (HASBIAS) bv4 = *(const float4*)(bias + n0 + tx * 4);
    #pragma unroll
    for (int i = 0; i < 4; i++) {
        int row = m0 + ty * 4 + i;
        float4 out;
        out.x = acc[i][0] * alpha; out.y = acc[i][1] * alpha;
        out.z = acc[i][2] * alpha; out.w = acc[i][3] * alpha;
        if (HASBIAS) { out.x += bv4.x; out.y += bv4.y; out.z += bv4.z; out.w += bv4.w; }
        if (HASD) {
            float4 dv = *(const float4*)(D + (size_t)row * ldc + n0 + tx * 4);
            out.x += dv.x; out.y += dv.y; out.z += dv.z; out.w += dv.w;
        }
        if (RELU) {
            out.x = fmaxf(out.x, 0.f); out.y = fmaxf(out.y, 0.f);
            out.z = fmaxf(out.z, 0.f); out.w = fmaxf(out.w, 0.f);
        }
        *(float4*)(C + (size_t)row * ldc + n0 + tx * 4) = out;
    }
}

// ------------------------------ slot build + LN(q) -------------------------
__global__ void __launch_bounds__(256) build_slots_kernel(
    const float* __restrict__ lnqg, const float* __restrict__ lnqb)
{
    __shared__ float sm[16];
    int r = blockIdx.x;
    int bv = r >> 3, s = r & 7;
    int b = bv >> 2;
    int t = threadIdx.x;
    float val = (t < SVD) ? g_sview[bv * SVD + t]
                          : g_sattr[(b * NS + s) * SAD + (t - SVD)];
    float s1 = val, s2 = val * val;
    block_sum2(s1, s2, sm);
    float mu = s1 * (1.f / 256.f);
    float var = s2 * (1.f / 256.f) - mu * mu;
    float rs = rsqrtf(var + 1e-5f);
    g_h[r * 256 + t] = val;
    g_qln[r * 256 + t] = (val - mu) * rs * lnqg[t] + lnqb[t];
}

// ------------------------------ fused attention v2 -------------------------
// Block = (batch b, 128-token chunk c).
// Phase 1: raw logits, split-tree reduce (16 shfl), lanes store raw l to smem.
// Softmax pass: one thread per token, 8 exps each, rowsum partials.
// Phase 2: upart[s][f] = sum_t e*x with packed f32x2 FFMA.
__global__ void __launch_bounds__(256) attn_fused_kernel()
{
    extern __shared__ char smraw[];
    __nv_bfloat16* xs = (__nv_bfloat16*)smraw;            // 128*256 bf16 = 64 KB
    float* es = (float*)(smraw + CHUNK * 256 * 2);        // 8*128 f32 = 4 KB
    float* rpart = (float*)(smraw + CHUNK * 256 * 2 + 8 * CHUNK * 4);  // 4*8 f32

    int b = blockIdx.x >> 5;
    int c = blockIdx.x & 31;
    int n0 = c * CHUNK;

    // stage xn tile
    {
        const uint4* src = (const uint4*)(g_xnb + ((size_t)b * NTOK + n0) * 256);
        uint4* dst = (uint4*)xs;
        #pragma unroll
        for (int i = 0; i < 16; i++)
            dst[threadIdx.x + 256 * i] = src[threadIdx.x + 256 * i];
    }

    int w = threadIdx.x >> 5, lane = threadIdx.x & 31;
    float q[8][8];
    {
        const float* qb = g_qproj + b * 2048;
        #pragma unroll
        for (int s = 0; s < 8; s++)
            #pragma unroll
            for (int j = 0; j < 8; j++)
                q[s][j] = qb[s * 256 + lane + 32 * j];
    }
    __syncthreads();

    // phase 1: raw logits; a[tok*8+s]
    #pragma unroll 1
    for (int p = 0; p < 8; p++) {
        int t0 = w * 16 + p * 2;
        const __nv_bfloat16* xp = xs + t0 * 256;
        float a[16];
        #pragma unroll
        for (int i = 0; i < 16; i++) a[i] = 0.f;
        #pragma unroll
        for (int j = 0; j < 8; j++) {
            float x0 = __bfloat162float(xp[lane + 32 * j]);
            float x1 = __bfloat162float(xp[256 + lane + 32 * j]);
            #pragma unroll
            for (int s = 0; s < 8; s++) {
                a[s]     += x0 * q[s][j];
                a[8 + s] += x1 * q[s][j];
            }
        }
        // split-tree reduction: idx bit3<-l4, bit2<-l3, bit1<-l2, bit0<-l1
        {
            int k1 = (lane >> 4) & 1;
            #pragma unroll
            for (int i = 0; i < 8; i++) {
                float send = k1 ? a[i] : a[i + 8];
                float recv = __shfl_xor_sync(0xffffffffu, send, 16);
                a[i] = (k1 ? a[i + 8] : a[i]) + recv;
            }
            int k2 = (lane >> 3) & 1;
            #pragma unroll
            for (int i = 0; i < 4; i++) {
                float send = k2 ? a[i] : a[i + 4];
                float recv = __shfl_xor_sync(0xffffffffu, send, 8);
                a[i] = (k2 ? a[i + 4] : a[i]) + recv;
            }
            int k3 = (lane >> 2) & 1;
            #pragma unroll
            for (int i = 0; i < 2; i++) {
                float send = k3 ? a[i] : a[i + 2];
                float recv = __shfl_xor_sync(0xffffffffu, send, 4);
                a[i] = (k3 ? a[i + 2] : a[i]) + recv;
            }
            int k4 = (lane >> 1) & 1;
            {
                float send = k4 ? a[0] : a[1];
                float recv = __shfl_xor_sync(0xffffffffu, send, 2);
                a[0] = (k4 ? a[1] : a[0]) + recv;
            }
            a[0] += __shfl_xor_sync(0xffffffffu, a[0], 1);
        }
        if (!(lane & 1)) {
            int tok = (lane >> 4) & 1;
            int s = ((lane >> 3) & 1) * 4 + ((lane >> 2) & 1) * 2 + ((lane >> 1) & 1);
            es[s * 128 + t0 + tok] = a[0];
        }
    }
    __syncthreads();

    // slot softmax: one thread per token
    if (threadIdx.x < 128) {
        int t = threadIdx.x;
        float l[8];
        #pragma unroll
        for (int s = 0; s < 8; s++) l[s] = es[s * 128 + t];
        float m = l[0];
        #pragma unroll
        for (int s = 1; s < 8; s++) m = fmaxf(m, l[s]);
        float e[8], sum = 0.f;
        #pragma unroll
        for (int s = 0; s < 8; s++) { e[s] = __expf(l[s] - m); sum += e[s]; }
        float inv = __frcp_rn(sum);
        #pragma unroll
        for (int s = 0; s < 8; s++) { e[s] *= inv; es[s * 128 + t] = e[s]; }
        // rowsum partials: split-tree over 8 values, 32 lanes
        {
            int k1 = (lane >> 4) & 1;
            #pragma unroll
            for (int i = 0; i < 4; i++) {
                float send = k1 ? e[i] : e[i + 4];
                float recv = __shfl_xor_sync(0xffffffffu, send, 16);
                e[i] = (k1 ? e[i + 4] : e[i]) + recv;
            }
            int k2 = (lane >> 3) & 1;
            #pragma unroll
            for (int i = 0; i < 2; i++) {
                float send = k2 ? e[i] : e[i + 2];
                float recv = __shfl_xor_sync(0xffffffffu, send, 8);
                e[i] = (k2 ? e[i + 2] : e[i]) + recv;
            }
            int k3 = (lane >> 2) & 1;
            {
                float send = k3 ? e[0] : e[1];
                float recv = __shfl_xor_sync(0xffffffffu, send, 4);
                e[0] = (k3 ? e[1] : e[0]) + recv;
            }
            e[0] += __shfl_xor_sync(0xffffffffu, e[0], 2);
            e[0] += __shfl_xor_sync(0xffffffffu, e[0], 1);
            if (!(lane & 3)) {
                int s = ((lane >> 4) & 1) * 4 + ((lane >> 3) & 1) * 2 + ((lane >> 2) & 1);
                rpart[(t >> 5) * 8 + s] = e[0];
            }
        }
    }
    __syncthreads();
    if (threadIdx.x < 8)
        g_rspart[c * ROWS + b * 8 + threadIdx.x] =
            rpart[threadIdx.x] + rpart[8 + threadIdx.x] +
            rpart[16 + threadIdx.x] + rpart[24 + threadIdx.x];

    // phase 2: upart[s][f] = sum_t e[s][t]*x[t][f] with f32x2
    int f = threadIdx.x;
    unsigned long long acc2[8];
    #pragma unroll
    for (int s = 0; s < 8; s++) acc2[s] = 0ull;
    #pragma unroll 2
    for (int t = 0; t < 128; t += 4) {
        float x0 = __bfloat162float(xs[(t + 0) * 256 + f]);
        float x1 = __bfloat162float(xs[(t + 1) * 256 + f]);
        float x2 = __bfloat162float(xs[(t + 2) * 256 + f]);
        float x3 = __bfloat162float(xs[(t + 3) * 256 + f]);
        unsigned long long p01 = pack2(x0, x1);
        unsigned long long p23 = pack2(x2, x3);
        #pragma unroll
        for (int s = 0; s < 8; s++) {
            ulonglong2 ev = *(const ulonglong2*)&es[s * 128 + t];
            ffma2(acc2[s], ev.x, p01);
            ffma2(acc2[s], ev.y, p23);
        }
    }
    #pragma unroll
    for (int s = 0; s < 8; s++) {
        float2 u = unpack2(acc2[s]);
        g_upart[((size_t)c * ROWS + b * 8 + s) * 256 + f] = u.x + u.y;
    }
}

// ------------------------------ reduce partials + normalize ----------------
__global__ void __launch_bounds__(256) ureduce_kernel()
{
    int r = blockIdx.x;
    int f = threadIdx.x;
    float s = 0.f;
    #pragma unroll
    for (int c = 0; c < NCHUNK; c++)
        s += g_upart[((size_t)c * ROWS + r) * 256 + f];
    float rs = 0.f;
    #pragma unroll
    for (int c = 0; c < NCHUNK; c++) rs += g_rspart[c * ROWS + r];
    g_upre[r * 256 + f] = s / rs;
}

// ------------------------------ GRU + LN(x_main) ---------------------------
__global__ void __launch_bounds__(256) gru_kernel(
    const float* __restrict__ lnrg, const float* __restrict__ lnrb)
{
    __shared__ float sm[16];
    int r = blockIdx.x;
    int j = threadIdx.x;
    float ir = g_gi[r * 768 + j],       hr = g_gh[r * 768 + j];
    float iz = g_gi[r * 768 + 256 + j], hz = g_gh[r * 768 + 256 + j];
    float inn = g_gi[r * 768 + 512 + j], hn = g_gh[r * 768 + 512 + j];
    float rg = sigmoidf(ir + hr);
    float z = sigmoidf(iz + hz);
    float nn = tanhf(inn + rg * hn);
    float hv = g_h[r * 256 + j];
    float xm = (1.f - z) * nn + z * hv;
    g_xmain[r * 256 + j] = xm;
    float s1 = xm, s2 = xm * xm;
    block_sum2(s1, s2, sm);
    float mu = s1 * (1.f / 256.f);
    float var = s2 * (1.f / 256.f) - mu * mu;
    float rs = rsqrtf(var + 1e-5f);
    g_rln[r * 256 + j] = (xm - mu) * rs * lnrg[j] + lnrb[j];
}

// ------------------------------ means -> slot_view / slot_attr -------------
__global__ void __launch_bounds__(256) means_kernel()
{
    int i = blockIdx.x * 256 + threadIdx.x;
    if (i < BVDIM * SVD) {
        int bv = i >> 6, c = i & 63;
        float s = 0.f;
        #pragma unroll
        for (int s8 = 0; s8 < 8; s8++) s += g_snew[((bv << 3) + s8) * 256 + c];
        g_sview[i] = s * 0.125f;
    } else if (i < BVDIM * SVD + 16 * NS * SAD) {
        int j = i - BVDIM * SVD;
        int bs = j / SAD, c = j % SAD;
        int b = bs >> 3, s = bs & 7;
        float t = 0.f;
        #pragma unroll
        for (int v = 0; v < 4; v++)
            t += g_snew[((b * 4 + v) * 8 + s) * 256 + SVD + c];
        g_sattr[j] = t * 0.25f;
    }
}

// ------------------------------ output copy --------------------------------
__global__ void __launch_bounds__(256) copy_out_kernel(float* __restrict__ out, int out_size)
{
    int i = blockIdx.x * 256 + threadIdx.x;
    if (i >= out_size) return;
    if (i < BVDIM * SVD) out[i] = g_sview[i];
    else out[i] = g_sattr[i - BVDIM * SVD];
}

// ------------------------------ host side ----------------------------------
template <typename T>
static float* sym_addr(const T& sym) {
    void* p = nullptr;
    cudaGetSymbolAddress(&p, sym);
    return (float*)p;
}

static void gemm(int M, int N, int K,
                 const float* A, int lda, const float* B, int ldb,
                 float* C, int ldc,
                 const float* bias, const float* D, float alpha,
                 bool transb, bool relu)
{
    dim3 grid(N / 64, M / 64);
    if (transb) {
        if (bias) gemm_k<true, false, true, false><<<grid, 256>>>(M, N, K, A, lda, B, ldb, C, ldc, bias, D, alpha);
        else      gemm_k<true, false, false, false><<<grid, 256>>>(M, N, K, A, lda, B, ldb, C, ldc, bias, D, alpha);
    } else {
        if (relu)       gemm_k<false, true, true, false><<<grid, 256>>>(M, N, K, A, lda, B, ldb, C, ldc, bias, D, alpha);
        else if (D)     gemm_k<false, false, true, true><<<grid, 256>>>(M, N, K, A, lda, B, ldb, C, ldc, bias, D, alpha);
        else if (bias)  gemm_k<false, false, true, false><<<grid, 256>>>(M, N, K, A, lda, B, ldb, C, ldc, bias, D, alpha);
        else            gemm_k<false, false, false, false><<<grid, 256>>>(M, N, K, A, lda, B, ldb, C, ldc, bias, D, alpha);
    }
}

extern "C" void kernel_launch(void* const* d_in, const int* in_sizes, int n_in,
                              void* d_out, int out_size)
{
    const float* x             = (const float*)d_in[0];
    const float* noise_view    = (const float*)d_in[1];
    const float* noise_attr    = (const float*)d_in[2];
    const float* view_loc      = (const float*)d_in[3];
    const float* view_log_scl  = (const float*)d_in[4];
    const float* attr_loc      = (const float*)d_in[5];
    const float* attr_log_scl  = (const float*)d_in[6];
    const float* ln_kv_g       = (const float*)d_in[7];
    const float* ln_kv_b       = (const float*)d_in[8];
    const float* W_kv          = (const float*)d_in[9];
    const float* ln_q_g        = (const float*)d_in[10];
    const float* ln_q_b        = (const float*)d_in[11];
    const float* W_qry         = (const float*)d_in[12];
    const float* w_ih          = (const float*)d_in[13];
    const float* w_hh          = (const float*)d_in[14];
    const float* b_ih          = (const float*)d_in[15];
    const float* b_hh          = (const float*)d_in[16];
    const float* ln_r_g        = (const float*)d_in[17];
    const float* ln_r_b        = (const float*)d_in[18];
    const float* W_r1          = (const float*)d_in[19];
    const float* b_r1          = (const float*)d_in[20];
    const float* W_r2          = (const float*)d_in[21];
    const float* b_r2          = (const float*)d_in[22];

    float* pMcomb = sym_addr(g_Mcomb);
    float* pMvih  = sym_addr(g_Mvih);
    float* pqln   = sym_addr(g_qln);
    float* pqproj = sym_addr(g_qproj);
    float* pupre  = sym_addr(g_upre);
    float* ph     = sym_addr(g_h);
    float* pgi    = sym_addr(g_gi);
    float* pgh    = sym_addr(g_gh);
    float* prln   = sym_addr(g_rln);
    float* pt1    = sym_addr(g_t1);
    float* pxmain = sym_addr(g_xmain);
    float* psnew  = sym_addr(g_snew);

    const int attn_smem = CHUNK * 256 * 2 + 8 * CHUNK * 4 + 32 * 4;
    static bool attr_set = false;
    if (!attr_set) {
        cudaFuncSetAttribute(attn_fused_kernel,
                             cudaFuncAttributeMaxDynamicSharedMemorySize, attn_smem);
        attr_set = true;
    }

    // xn = bf16(LN(x))
    ln_x_kernel<<<32768, 256>>>(x, ln_kv_g, ln_kv_b);
    // slot init
    slots_init_kernel<<<112, 256>>>(noise_view, noise_attr, view_loc, view_log_scl,
                                    attr_loc, attr_log_scl);
    // M_comb = coef * W_qry @ W_k^T      (W_k = W_kv[:, :128])
    gemm(256, 256, 128, W_qry, 128, W_kv, 384, pMcomb, 256, nullptr, nullptr, COEF, true, false);
    // M_vih = W_v @ w_ih^T               (W_v = W_kv[:, 128:384])
    gemm(256, 768, 256, W_kv + 128, 384, w_ih, 256, pMvih, 768, nullptr, nullptr, 1.f, true, false);

    for (int step = 0; step < 3; step++) {
        build_slots_kernel<<<ROWS, 256>>>(ln_q_g, ln_q_b);
        // gh = h @ w_hh^T + b_hh   (only depends on build_slots)
        gemm(ROWS, 768, 256, ph, 256, w_hh, 256, pgh, 768, b_hh, nullptr, 1.f, true, false);
        // q_proj = q_ln @ M_comb
        gemm(ROWS, 256, 256, pqln, 256, pMcomb, 256, pqproj, 256, nullptr, nullptr, 1.f, false, false);
        attn_fused_kernel<<<BVDIM * NCHUNK, 256, attn_smem>>>();
        ureduce_kernel<<<ROWS, 256>>>();
        // gi = upre @ M_vih + b_ih   (x_upd GEMM folded away)
        gemm(ROWS, 768, 256, pupre, 256, pMvih, 768, pgi, 768, b_ih, nullptr, 1.f, false, false);
        gru_kernel<<<ROWS, 256>>>(ln_r_g, ln_r_b);
        // t1 = relu(r_ln @ W_r1 + b_r1)
        gemm(ROWS, 512, 256, prln, 256, W_r1, 512, pt1, 512, b_r1, nullptr, 1.f, false, true);
        // slot_new = x_main + t1 @ W_r2 + b_r2
        gemm(ROWS, 256, 512, pt1, 512, W_r2, 256, psnew, 256, b_r2, pxmain, 1.f, false, false);
        means_kernel<<<112, 256>>>();
    }

    copy_out_kernel<<<(out_size + 255) / 256, 256>>>((float*)d_out, out_size);
}